// round 9
// baseline (speedup 1.0000x reference)
#include <cuda_runtime.h>
#include <cuda_fp16.h>
#include <cstdint>
#include <math.h>

#define DEV_INLINE __device__ __forceinline__

// Problem dims (fixed by the dataset)
constexpr int B_ = 128, T_ = 512, F_ = 512, M_ = 512;
constexpr float LN_EPS = 1e-5f;

// GEMM tiling: CTA 128(m) x 128(f) x 32(k); 8 warps of 32x64; fp16 mma k16
constexpr int BM = 128, BN = 128, BK = 32;
constexpr int NKC = T_ / BK;     // 16 k-chunks
constexpr int THREADS = 256;
constexpr int NSTAGE = 3;

// Smem layout (floats / bytes)
constexpr int A_STAGE_B  = BM * BK * 2;            // 8192 B fp16 A-frags
constexpr int XRAW_ROW   = 132;                    // 128 + 4 pad floats
constexpr int XRAW_B     = BK * XRAW_ROW * 4;      // 16896 B raw x tile (f32)
constexpr int STAGE_B    = A_STAGE_B + XRAW_B;     // 25088 B
constexpr int BFRAG_B    = BN * BK * 2;            // 8192 B packed fp16 B-frags (single buf)
constexpr int GB_OFF     = NSTAGE * STAGE_B + BFRAG_B;          // gamma offset
constexpr int SMEM_BYTES = GB_OFF + 2 * T_ * 4;    // + gamma/beta = 87552 B

// Device scratch (no allocation allowed)
__device__ float g_s[4][B_ * F_];                  // LN partial sums (T quarters)
__device__ float g_ss[4][B_ * F_];
__device__ uint4 g_WfragH[32 * 16 * 2 * 32];       // 512KB: [m16][kc][kstep][lane]

// ---------------- helpers ----------------
DEV_INLINE uint32_t smem_u32(const void* p) {
    uint32_t a;
    asm("{ .reg .u64 t; cvta.to.shared.u64 t, %1; cvt.u32.u64 %0, t; }"
        : "=r"(a) : "l"(p));
    return a;
}

DEV_INLINE uint32_t h2pack(float a, float b) {
    __half2 h = __floats2half2_rn(a, b);
    return *reinterpret_cast<uint32_t*>(&h);
}

DEV_INLINE void cp_async16(uint32_t dst_smem, const void* src) {
    asm volatile(
        "{\n\t.reg .u64 g;\n\tcvta.to.global.u64 g, %1;\n\t"
        "cp.async.cg.shared.global [%0], [g], 16;\n\t}"
        :: "r"(dst_smem), "l"(src));
}
DEV_INLINE void cp_commit() { asm volatile("cp.async.commit_group;"); }
template <int N> DEV_INLINE void cp_wait() {
    asm volatile("cp.async.wait_group %0;" :: "n"(N));
}

// m16n8k16 fp16 mma, fp32 accumulate
DEV_INLINE void mma_f16(float* c, const uint32_t* a, uint32_t b0, uint32_t b1) {
    asm volatile(
        "mma.sync.aligned.m16n8k16.row.col.f32.f16.f16.f32 "
        "{%0,%1,%2,%3}, {%4,%5,%6,%7}, {%8,%9}, {%0,%1,%2,%3};"
        : "+f"(c[0]), "+f"(c[1]), "+f"(c[2]), "+f"(c[3])
        : "r"(a[0]), "r"(a[1]), "r"(a[2]), "r"(a[3]), "r"(b0), "r"(b1));
}

DEV_INLINE float gelu_exact(float v) {
    return 0.5f * v * (1.0f + erff(v * 0.70710678118654752f));
}

// ---------------- kernel 1: LN partial sums (T split in 4) ----------------
__global__ __launch_bounds__(256) void ln_partial_kernel(const float* __restrict__ x) {
    const int tq = blockIdx.x & 3;
    const int fc = (blockIdx.x >> 2) & 1;
    const int b  = blockIdx.x >> 3;
    const int f  = fc * 256 + threadIdx.x;
    const float* xp = x + ((size_t)b * T_ + tq * 128) * F_ + f;
    float s = 0.f, ss = 0.f;
#pragma unroll 8
    for (int t = 0; t < 128; t++) {
        float v = xp[(size_t)t * F_];
        s += v;
        ss += v * v;
    }
    g_s[tq][b * F_ + f]  = s;
    g_ss[tq][b * F_ + f] = ss;
}

// ---------------- kernel 2: pack W into fp16 A-fragment order ----------------
// [m16 (32)][kc (16)][kstep (2)][lane (32)] -> uint4 (8 halfs)
__global__ __launch_bounds__(256) void pack_w_kernel(const float* __restrict__ W) {
    int lin = blockIdx.x * 256 + threadIdx.x;      // 32768 uint4s
    int lane = lin & 31;
    int kstep = (lin >> 5) & 1;
    int kc = (lin >> 6) & 15;
    int m16 = lin >> 10;
    int g = lane >> 2, tig = lane & 3;
    int mr = m16 * 16 + g;
    int tc = kc * 32 + kstep * 16 + 2 * tig;
    const float* w0 = W + (size_t)mr * T_ + tc;
    const float* w8 = W + (size_t)(mr + 8) * T_ + tc;
    uint4 v;
    v.x = h2pack(w0[0], w0[1]);
    v.y = h2pack(w8[0], w8[1]);
    v.z = h2pack(w0[8], w0[9]);
    v.w = h2pack(w8[8], w8[9]);
    g_WfragH[lin] = v;
}

// ---------------- kernel 3: fused LN + pack + fp16 GEMM + GELU + residual ----------
__global__ __launch_bounds__(THREADS, 2)
void timemix_gemm_kernel(const float* __restrict__ x,
                         const float* __restrict__ gamma,
                         const float* __restrict__ beta,
                         const float* __restrict__ bvec,
                         float* __restrict__ out) {
    extern __shared__ char smem[];
    const int tid = threadIdx.x;
    const int wid = tid >> 5, lane = tid & 31;
    const int wm = wid & 3, wn = wid >> 2;          // 4 x 2 warps (32m x 64f)
    const int g = lane >> 2, tig = lane & 3;
    const int bm = blockIdx.x;                      // 0..3
    const int ft = blockIdx.y;                      // 0..3
    const int b = blockIdx.z;

    const uint32_t smem_base = smem_u32(smem);
    uint4* sBfrag = reinterpret_cast<uint4*>(smem + NSTAGE * STAGE_B);
    float* s_gamma = reinterpret_cast<float*>(smem + GB_OFF);
    float* s_beta  = s_gamma + T_;

    // stage gamma/beta
#pragma unroll
    for (int r = 0; r < 2; r++) {
        int i = tid + r * 256;
        s_gamma[i] = gamma[i];
        s_beta[i]  = beta[i];
    }

    // per-thread LN stats for its two pack columns: f0 = np*16+g, f0+8
    const int pk_np = tid >> 5;                     // pack np = tid/32
    float mu0, rs0, m20, mu1, rs1, m21;
    {
        int fg0 = b * F_ + ft * 128 + pk_np * 16 + g;
        float sm = g_s[0][fg0] + g_s[1][fg0] + g_s[2][fg0] + g_s[3][fg0];
        float sq = g_ss[0][fg0] + g_ss[1][fg0] + g_ss[2][fg0] + g_ss[3][fg0];
        mu0 = sm * (1.0f / T_);
        rs0 = rsqrtf(fmaxf(sq * (1.0f / T_) - mu0 * mu0, 0.0f) + LN_EPS);
        m20 = mu0 * rs0;
        int fg1 = fg0 + 8;
        sm = g_s[0][fg1] + g_s[1][fg1] + g_s[2][fg1] + g_s[3][fg1];
        sq = g_ss[0][fg1] + g_ss[1][fg1] + g_ss[2][fg1] + g_ss[3][fg1];
        mu1 = sm * (1.0f / T_);
        rs1 = rsqrtf(fmaxf(sq * (1.0f / T_) - mu1 * mu1, 0.0f) + LN_EPS);
        m21 = mu1 * rs1;
    }

    auto load_stage = [&](int kc) {
        uint32_t sA = smem_base + (kc % NSTAGE) * STAGE_B;
        uint32_t sX = sA + A_STAGE_B;
#pragma unroll
        for (int r = 0; r < 2; r++) {               // A: 512 uint4s
            int i = tid + r * 256;
            int m16l = i >> 6;
            int off = i & 63;                       // ks*32 + lane
            const uint4* src = g_WfragH + ((size_t)(bm * 8 + m16l) * 16 + kc) * 64 + off;
            cp_async16(sA + i * 16, src);
        }
#pragma unroll
        for (int r = 0; r < 4; r++) {               // Xraw: 1024 float4s
            int i = tid + r * 256;
            int t = i >> 5;
            int c = i & 31;
            const float* src = x + ((size_t)b * T_ + kc * 32 + t) * F_ + ft * 128 + c * 4;
            cp_async16(sX + t * (XRAW_ROW * 4) + c * 16, src);
        }
        cp_commit();
    };

    float acc[2][8][4];
#pragma unroll
    for (int i = 0; i < 2; i++)
#pragma unroll
        for (int j = 0; j < 8; j++)
#pragma unroll
            for (int r = 0; r < 4; r++) acc[i][j][r] = 0.0f;

    load_stage(0);
    load_stage(1);

    for (int kc = 0; kc < NKC; kc++) {
        if (kc + 1 < NKC) cp_wait<1>(); else cp_wait<0>();
        __syncthreads();   // stage kc ready; also protects Bfrag from prev mma readers

        const float* sX = reinterpret_cast<const float*>(
            smem + (kc % NSTAGE) * STAGE_B + A_STAGE_B);

        // ---- pack phase: normalize x tile -> fp16 B-frags (2 uint4/thread) ----
        {
            const int k0 = kc * 32;
            const int fl0 = pk_np * 16 + g;          // local f of column 0
#pragma unroll
            for (int ks = 0; ks < 2; ks++) {
                int t0 = ks * 16 + 2 * tig;
                float ga0 = s_gamma[k0 + t0],     be0 = s_beta[k0 + t0];
                float ga1 = s_gamma[k0 + t0 + 1], be1 = s_beta[k0 + t0 + 1];
                float ga8 = s_gamma[k0 + t0 + 8], be8 = s_beta[k0 + t0 + 8];
                float ga9 = s_gamma[k0 + t0 + 9], be9 = s_beta[k0 + t0 + 9];
                const float* r0 = sX + t0 * XRAW_ROW + fl0;
                const float* r1 = r0 + XRAW_ROW;
                const float* r8 = r0 + 8 * XRAW_ROW;
                const float* r9 = r0 + 9 * XRAW_ROW;
                uint4 v;
                v.x = h2pack(fmaf(r0[0], rs0 * ga0, fmaf(-m20, ga0, be0)),
                             fmaf(r1[0], rs0 * ga1, fmaf(-m20, ga1, be1)));
                v.y = h2pack(fmaf(r8[0], rs0 * ga8, fmaf(-m20, ga8, be8)),
                             fmaf(r9[0], rs0 * ga9, fmaf(-m20, ga9, be9)));
                v.z = h2pack(fmaf(r0[8], rs1 * ga0, fmaf(-m21, ga0, be0)),
                             fmaf(r1[8], rs1 * ga1, fmaf(-m21, ga1, be1)));
                v.w = h2pack(fmaf(r8[8], rs1 * ga8, fmaf(-m21, ga8, be8)),
                             fmaf(r9[8], rs1 * ga9, fmaf(-m21, ga9, be9)));
                sBfrag[(pk_np * 2 + ks) * 32 + lane] = v;
            }
        }
        __syncthreads();   // B-frags ready

        // ---- mma phase ----
        const uint4* sA = reinterpret_cast<const uint4*>(smem + (kc % NSTAGE) * STAGE_B);
#pragma unroll
        for (int kstep = 0; kstep < 2; kstep++) {
            uint32_t a[2][4];
#pragma unroll
            for (int i = 0; i < 2; i++) {
                uint4 v = sA[((wm * 2 + i) * 2 + kstep) * 32 + lane];
                a[i][0] = v.x; a[i][1] = v.y; a[i][2] = v.z; a[i][3] = v.w;
            }
            uint4 bf[4];
#pragma unroll
            for (int jp = 0; jp < 4; jp++)
                bf[jp] = sBfrag[((wn * 4 + jp) * 2 + kstep) * 32 + lane];
#pragma unroll
            for (int i = 0; i < 2; i++)
#pragma unroll
                for (int jp = 0; jp < 4; jp++) {
                    mma_f16(acc[i][2 * jp + 0], a[i], bf[jp].x, bf[jp].y);
                    mma_f16(acc[i][2 * jp + 1], a[i], bf[jp].z, bf[jp].w);
                }
        }

        // prefetch kc+2 into stage (kc+2)%3 (not read by anyone until its wait)
        if (kc + 2 < NKC) load_stage(kc + 2);
    }

    // ---- epilogue: bias + exact GELU + residual ----
    const int m_warp = bm * 128 + wm * 32;
    const int f_warp = ft * 128 + wn * 64;
#pragma unroll
    for (int i = 0; i < 2; i++) {
#pragma unroll
        for (int h = 0; h < 2; h++) {
            int m = m_warp + i * 16 + g + 8 * h;
            float bv = bvec[m];
            const float* xr = x + ((size_t)b * M_ + m) * F_ + f_warp;
            float* yr = out + ((size_t)b * M_ + m) * F_ + f_warp;
#pragma unroll
            for (int j = 0; j < 8; j++) {
                int fo = j * 8 + tig * 2;
                float2 xv = *reinterpret_cast<const float2*>(xr + fo);
                float2 o;
                o.x = gelu_exact(acc[i][j][2 * h + 0] + bv) + xv.x;
                o.y = gelu_exact(acc[i][j][2 * h + 1] + bv) + xv.y;
                *reinterpret_cast<float2*>(yr + fo) = o;
            }
        }
    }
}

// ---------------- launch ----------------
extern "C" void kernel_launch(void* const* d_in, const int* in_sizes, int n_in,
                              void* d_out, int out_size) {
    const float* x     = (const float*)d_in[0];
    const float* gamma = (const float*)d_in[1];
    const float* beta  = (const float*)d_in[2];
    const float* W     = (const float*)d_in[3];
    const float* bvec  = (const float*)d_in[4];
    float* out = (float*)d_out;

    cudaFuncSetAttribute(timemix_gemm_kernel,
                         cudaFuncAttributeMaxDynamicSharedMemorySize, SMEM_BYTES);

    ln_partial_kernel<<<B_ * 4 * 2, 256>>>(x);
    pack_w_kernel<<<32768 / 256, 256>>>(W);
    {
        dim3 grid(M_ / BM, F_ / BN, B_);   // (4, 4, 128)
        timemix_gemm_kernel<<<grid, THREADS, SMEM_BYTES>>>(x, gamma, beta, bvec, out);
    }
}